// round 1
// baseline (speedup 1.0000x reference)
#include <cuda_runtime.h>
#include <cuda_bf16.h>
#include <math.h>

// Problem constants
#define B_  2
#define S_  2048
#define DM_ 2048
#define NH_ 16
#define HD_ 128
#define BS_ (B_ * S_)        // 4096 rows for all GEMMs
#define SCALE_ 0.08838834764831845f   // 1/sqrt(128)

// ---------------------------------------------------------------------------
// Scratch (static __device__ arrays per harness rules: no allocations)
// ---------------------------------------------------------------------------
__device__ float g_q[B_ * NH_ * S_ * HD_];   // [bh][s][d]
__device__ float g_k[B_ * NH_ * S_ * HD_];
__device__ float g_v[B_ * NH_ * S_ * HD_];
__device__ float g_ctx[BS_ * DM_];           // [b*S+s][dm]
__device__ float g_cos[S_ * (HD_ / 2)];
__device__ float g_sin[S_ * (HD_ / 2)];

// ---------------------------------------------------------------------------
// RoPE table: cos/sin(s * inv_freq_i), computed in double for accuracy.
// ---------------------------------------------------------------------------
__global__ void rope_table_kernel() {
    int idx = blockIdx.x * blockDim.x + threadIdx.x;
    if (idx >= S_ * (HD_ / 2)) return;
    int s = idx / (HD_ / 2);
    int i = idx % (HD_ / 2);
    double inv_freq = exp(-((double)(2 * i) / (double)HD_) * log(10000.0));
    double ang = (double)s * inv_freq;
    g_cos[idx] = (float)cos(ang);
    g_sin[idx] = (float)sin(ang);
}

// ---------------------------------------------------------------------------
// SGEMM: C[M=4096, N=2048] = A[4096,2048] @ W[2048,2048] + bias
// 128x128 tile, BK=8, 256 threads, 8x8 microtile per thread.
// mode 0: rope + scatter to [bh][s][d]   (Q, K)
// mode 1: scatter to [bh][s][d], no rope (V)
// mode 2: plain row-major write          (output projection)
// ---------------------------------------------------------------------------
#define GM 4096
#define GN 2048
#define GK 2048
#define TK 8

__global__ __launch_bounds__(256) void sgemm_kernel(
    const float* __restrict__ A, const float* __restrict__ W,
    const float* __restrict__ bias, float* __restrict__ C, int mode)
{
    __shared__ float As[TK][128];
    __shared__ float Bs[TK][128];

    const int tid = threadIdx.x;
    const int m0 = blockIdx.y * 128;
    const int n0 = blockIdx.x * 128;
    const int ty = tid >> 4;        // 0..15 -> row group of 8
    const int tx = tid & 15;        // 0..15 -> col group of 8

    const int arow = tid >> 1;           // 0..127
    const int ak   = (tid & 1) * 4;      // 0 or 4
    const int brow = tid >> 5;           // 0..7
    const int bc   = (tid & 31) * 4;     // 0..124

    float acc[8][8];
    #pragma unroll
    for (int i = 0; i < 8; i++)
        #pragma unroll
        for (int j = 0; j < 8; j++) acc[i][j] = 0.f;

    const float* Aptr = A + (size_t)(m0 + arow) * GK + ak;
    const float* Bptr = W + (size_t)brow * GN + n0 + bc;

    for (int k0 = 0; k0 < GK; k0 += TK) {
        float4 av = *(const float4*)(Aptr + k0);
        As[ak + 0][arow] = av.x;
        As[ak + 1][arow] = av.y;
        As[ak + 2][arow] = av.z;
        As[ak + 3][arow] = av.w;
        *(float4*)&Bs[brow][bc] = *(const float4*)(Bptr + (size_t)k0 * GN);
        __syncthreads();

        #pragma unroll
        for (int k = 0; k < TK; k++) {
            float a[8], b[8];
            *(float4*)(a + 0) = *(const float4*)&As[k][ty * 8];
            *(float4*)(a + 4) = *(const float4*)&As[k][ty * 8 + 4];
            *(float4*)(b + 0) = *(const float4*)&Bs[k][tx * 8];
            *(float4*)(b + 4) = *(const float4*)&Bs[k][tx * 8 + 4];
            #pragma unroll
            for (int i = 0; i < 8; i++)
                #pragma unroll
                for (int j = 0; j < 8; j++)
                    acc[i][j] += a[i] * b[j];
        }
        __syncthreads();
    }

    // Epilogue
    const int col0 = n0 + tx * 8;
    float bv[8];
    #pragma unroll
    for (int j = 0; j < 8; j++) bv[j] = bias[col0 + j];

    #pragma unroll
    for (int i = 0; i < 8; i++) {
        int m = m0 + ty * 8 + i;
        int b = m >> 11;          // / S_
        int s = m & (S_ - 1);
        float v[8];
        #pragma unroll
        for (int j = 0; j < 8; j++) v[j] = acc[i][j] + bv[j];

        if (mode == 0) {
            // RoPE: pairs (even, odd) within head dim
            int d0 = col0 & (HD_ - 1);
            #pragma unroll
            for (int p = 0; p < 4; p++) {
                int pi = (d0 >> 1) + p;
                float cs = g_cos[s * (HD_ / 2) + pi];
                float sn = g_sin[s * (HD_ / 2) + pi];
                float e = v[2 * p], o = v[2 * p + 1];
                v[2 * p]     = e * cs - o * sn;
                v[2 * p + 1] = o * cs + e * sn;
            }
        }
        if (mode <= 1) {
            int h = col0 >> 7;             // / HD_
            int d = col0 & (HD_ - 1);
            float* dst = C + (size_t)((b * NH_ + h) * S_ + s) * HD_ + d;
            *(float4*)(dst + 0) = *(float4*)(v + 0);
            *(float4*)(dst + 4) = *(float4*)(v + 4);
        } else {
            float* dst = C + (size_t)m * GN + col0;
            *(float4*)(dst + 0) = *(float4*)(v + 0);
            *(float4*)(dst + 4) = *(float4*)(v + 4);
        }
    }
}

// ---------------------------------------------------------------------------
// Flash attention (causal), fp32, BM=BN=64, 256 threads, online softmax.
// q/k/v: [BH][S][HD]  ->  ctx: [b*S+s][DM] (head slice)
// ---------------------------------------------------------------------------
#define BM 64
#define BN 64
#define QPAD 132
#define SPAD 68

__global__ __launch_bounds__(256) void attn_kernel(
    const float* __restrict__ q, const float* __restrict__ k,
    const float* __restrict__ v, float* __restrict__ ctx)
{
    extern __shared__ float sm[];
    float* Qs   = sm;                       // 64*132
    float* Ks   = Qs + BM * QPAD;           // 64*132
    float* Vs   = Ks + BN * QPAD;           // 64*132
    float* Ss   = Vs + BN * QPAD;           // 64*68
    float* mrow = Ss + BM * SPAD;           // 64
    float* lrow = mrow + BM;                // 64
    float* frow = lrow + BM;                // 64

    const int tid = threadIdx.x;
    const int bh  = blockIdx.y;
    const int qt  = gridDim.x - 1 - blockIdx.x;   // heavy tiles first
    const int q0  = qt * BM;

    const float* qp = q + ((size_t)bh * S_ + q0) * HD_;
    const float* kb = k + (size_t)bh * S_ * HD_;
    const float* vb = v + (size_t)bh * S_ * HD_;

    // Load Q tile (stays resident)
    for (int t = tid; t < BM * 32; t += 256) {
        int r = t >> 5, c = (t & 31) * 4;
        *(float4*)&Qs[r * QPAD + c] = *(const float4*)&qp[r * HD_ + c];
    }
    if (tid < BM) { mrow[tid] = -1e30f; lrow[tid] = 0.f; }

    const int ty = tid >> 4, tx = tid & 15;
    float acc_o[4][8];
    #pragma unroll
    for (int i = 0; i < 4; i++)
        #pragma unroll
        for (int j = 0; j < 8; j++) acc_o[i][j] = 0.f;

    const int nkv = qt + 1;
    for (int kt = 0; kt < nkv; kt++) {
        const int k0 = kt * BN;
        __syncthreads();  // prev PV done before overwriting K/V/S
        const float* kp = kb + (size_t)k0 * HD_;
        const float* vp = vb + (size_t)k0 * HD_;
        for (int t = tid; t < BN * 32; t += 256) {
            int r = t >> 5, c = (t & 31) * 4;
            *(float4*)&Ks[r * QPAD + c] = *(const float4*)&kp[r * HD_ + c];
            *(float4*)&Vs[r * QPAD + c] = *(const float4*)&vp[r * HD_ + c];
        }
        __syncthreads();

        // S = Q K^T (scaled, masked) -> Ss
        {
            const int r0 = ty * 4, c0 = tx * 4;
            float accs[4][4];
            #pragma unroll
            for (int i = 0; i < 4; i++)
                #pragma unroll
                for (int j = 0; j < 4; j++) accs[i][j] = 0.f;

            for (int kk = 0; kk < HD_; kk += 4) {
                float4 qa[4], kv[4];
                #pragma unroll
                for (int i = 0; i < 4; i++)
                    qa[i] = *(const float4*)&Qs[(r0 + i) * QPAD + kk];
                #pragma unroll
                for (int j = 0; j < 4; j++)
                    kv[j] = *(const float4*)&Ks[(c0 + j) * QPAD + kk];
                #pragma unroll
                for (int i = 0; i < 4; i++)
                    #pragma unroll
                    for (int j = 0; j < 4; j++)
                        accs[i][j] += qa[i].x * kv[j].x + qa[i].y * kv[j].y
                                    + qa[i].z * kv[j].z + qa[i].w * kv[j].w;
            }
            #pragma unroll
            for (int i = 0; i < 4; i++) {
                int qi = q0 + r0 + i;
                #pragma unroll
                for (int j = 0; j < 4; j++) {
                    int kj = k0 + c0 + j;
                    float sv = accs[i][j] * SCALE_;
                    if (kj > qi) sv = -1e30f;
                    Ss[(r0 + i) * SPAD + c0 + j] = sv;
                }
            }
        }
        __syncthreads();

        // Online softmax: 4 threads per row
        {
            const int row = tid >> 2, g = tid & 3;
            float tmax = -1e30f;
            for (int j = g; j < BN; j += 4)
                tmax = fmaxf(tmax, Ss[row * SPAD + j]);
            tmax = fmaxf(tmax, __shfl_xor_sync(0xffffffffu, tmax, 1));
            tmax = fmaxf(tmax, __shfl_xor_sync(0xffffffffu, tmax, 2));
            float mold = mrow[row];
            float mnew = fmaxf(mold, tmax);
            float sum = 0.f;
            for (int j = g; j < BN; j += 4) {
                float p = __expf(Ss[row * SPAD + j] - mnew);
                Ss[row * SPAD + j] = p;
                sum += p;
            }
            sum += __shfl_xor_sync(0xffffffffu, sum, 1);
            sum += __shfl_xor_sync(0xffffffffu, sum, 2);
            if (g == 0) {
                float f = __expf(mold - mnew);
                lrow[row] = lrow[row] * f + sum;
                mrow[row] = mnew;
                frow[row] = f;
            }
        }
        __syncthreads();

        // Rescale O, then O += P @ V
        {
            const int r0 = ty * 4, c0 = tx * 8;
            float fr[4];
            #pragma unroll
            for (int i = 0; i < 4; i++) fr[i] = frow[r0 + i];
            #pragma unroll
            for (int i = 0; i < 4; i++)
                #pragma unroll
                for (int j = 0; j < 8; j++) acc_o[i][j] *= fr[i];

            for (int j = 0; j < BN; j++) {
                float p[4];
                #pragma unroll
                for (int i = 0; i < 4; i++) p[i] = Ss[(r0 + i) * SPAD + j];
                float4 v0 = *(const float4*)&Vs[j * QPAD + c0];
                float4 v1 = *(const float4*)&Vs[j * QPAD + c0 + 4];
                #pragma unroll
                for (int i = 0; i < 4; i++) {
                    acc_o[i][0] += p[i] * v0.x;
                    acc_o[i][1] += p[i] * v0.y;
                    acc_o[i][2] += p[i] * v0.z;
                    acc_o[i][3] += p[i] * v0.w;
                    acc_o[i][4] += p[i] * v1.x;
                    acc_o[i][5] += p[i] * v1.y;
                    acc_o[i][6] += p[i] * v1.z;
                    acc_o[i][7] += p[i] * v1.w;
                }
            }
        }
    }
    __syncthreads();

    // Final normalize + write to ctx[b*S+s][h*HD + c]
    const int b = bh >> 4, h = bh & 15;
    const int r0 = ty * 4, c0 = tx * 8;
    #pragma unroll
    for (int i = 0; i < 4; i++) {
        int r = r0 + i;
        float inv = 1.f / lrow[r];
        int s = q0 + r;
        float* dst = ctx + (size_t)(b * S_ + s) * DM_ + h * HD_ + c0;
        float o[8];
        #pragma unroll
        for (int j = 0; j < 8; j++) o[j] = acc_o[i][j] * inv;
        *(float4*)(dst + 0) = *(float4*)(o + 0);
        *(float4*)(dst + 4) = *(float4*)(o + 4);
    }
}

// ---------------------------------------------------------------------------
// Launch
// ---------------------------------------------------------------------------
extern "C" void kernel_launch(void* const* d_in, const int* in_sizes, int n_in,
                              void* d_out, int out_size)
{
    const float* hs = (const float*)d_in[0];
    const float* Wq = (const float*)d_in[1];
    const float* bq = (const float*)d_in[2];
    const float* Wk = (const float*)d_in[3];
    const float* bk = (const float*)d_in[4];
    const float* Wv = (const float*)d_in[5];
    const float* bv = (const float*)d_in[6];
    const float* Wo = (const float*)d_in[7];
    const float* bo = (const float*)d_in[8];
    float* out = (float*)d_out;

    float *qd, *kd, *vd, *ctxd;
    cudaGetSymbolAddress((void**)&qd,   g_q);
    cudaGetSymbolAddress((void**)&kd,   g_k);
    cudaGetSymbolAddress((void**)&vd,   g_v);
    cudaGetSymbolAddress((void**)&ctxd, g_ctx);

    static int smem_set = 0;
    const int attn_smem = (3 * BM * QPAD + BM * SPAD + 3 * BM) * (int)sizeof(float);
    if (!smem_set) {
        cudaFuncSetAttribute(attn_kernel,
                             cudaFuncAttributeMaxDynamicSharedMemorySize,
                             attn_smem);
        smem_set = 1;
    }

    // 1. RoPE tables
    rope_table_kernel<<<(S_ * (HD_ / 2) + 255) / 256, 256>>>();

    // 2. QKV projections (bias + rope + transpose fused in epilogue)
    dim3 ggrid(GN / 128, GM / 128);
    sgemm_kernel<<<ggrid, 256>>>(hs, Wq, bq, qd, 0);
    sgemm_kernel<<<ggrid, 256>>>(hs, Wk, bk, kd, 0);
    sgemm_kernel<<<ggrid, 256>>>(hs, Wv, bv, vd, 1);

    // 3. Causal flash attention
    dim3 agrid(S_ / BM, B_ * NH_);
    attn_kernel<<<agrid, 256, attn_smem>>>(qd, kd, vd, ctxd);

    // 4. Output projection
    sgemm_kernel<<<ggrid, 256>>>(ctxd, Wo, bo, out, 2);
}

// round 2
// speedup vs baseline: 1.5794x; 1.5794x over previous
#include <cuda_runtime.h>
#include <cuda_bf16.h>
#include <math.h>

// Problem constants
#define B_  2
#define S_  2048
#define DM_ 2048
#define NH_ 16
#define HD_ 128
#define BS_ (B_ * S_)
#define SCALE_ 0.08838834764831845f   // 1/sqrt(128)

// ---------------------------------------------------------------------------
// Scratch
// ---------------------------------------------------------------------------
__device__ float g_q[B_ * NH_ * S_ * HD_];   // [bh][s][d]
__device__ float g_k[B_ * NH_ * S_ * HD_];
__device__ float g_v[B_ * NH_ * S_ * HD_];
__device__ float g_ctx[BS_ * DM_];           // [b*S+s][dm]
__device__ float g_cos[S_ * (HD_ / 2)];
__device__ float g_sin[S_ * (HD_ / 2)];

// ---------------------------------------------------------------------------
// RoPE table (double precision for accuracy)
// ---------------------------------------------------------------------------
__global__ void rope_table_kernel() {
    int idx = blockIdx.x * blockDim.x + threadIdx.x;
    if (idx >= S_ * (HD_ / 2)) return;
    int s = idx / (HD_ / 2);
    int i = idx % (HD_ / 2);
    double inv_freq = exp(-((double)(2 * i) / (double)HD_) * log(10000.0));
    double ang = (double)s * inv_freq;
    g_cos[idx] = (float)cos(ang);
    g_sin[idx] = (float)sin(ang);
}

// ---------------------------------------------------------------------------
// TF32 tensor-core GEMM: C[4096,2048] = A[4096,2048] @ W[2048,2048] + bias
// 128x128 CTA tile, BK=32, 8 warps (2x4), each warp 64x32 via m16n8k8 mma.
// mode 0: rope + scatter to [bh][s][d]   (Q, K)
// mode 1: scatter to [bh][s][d]          (V)
// mode 2: plain row-major write          (O proj)
// ---------------------------------------------------------------------------
#define GK 2048
#define GN 2048
#define SMS 136   // smem stride: 136 % 32 == 8 -> conflict-free frag loads

__device__ __forceinline__ unsigned f2tf32(float x) {
    unsigned r;
    asm("cvt.rna.tf32.f32 %0, %1;" : "=r"(r) : "f"(x));
    return r;
}

__global__ __launch_bounds__(256) void tgemm_kernel(
    const float* __restrict__ A, const float* __restrict__ W,
    const float* __restrict__ bias, float* __restrict__ C, int mode)
{
    __shared__ unsigned As[32][SMS];   // [k][m]
    __shared__ unsigned Bs[32][SMS];   // [k][n]

    const int tid  = threadIdx.x;
    const int lane = tid & 31, wid = tid >> 5;
    const int warpM = wid >> 2, warpN = wid & 3;     // 2 x 4
    const int gid = lane >> 2, tig = lane & 3;
    const int m0 = blockIdx.y * 128, n0 = blockIdx.x * 128;

    // global->reg staging assignments
    const int am  = tid & 127;        // A row within tile
    const int akq = tid >> 7;         // 0/1: which 16-wide k half
    const int bn  = (tid & 31) * 4;   // B col within tile
    const int bk  = tid >> 5;         // 0..7: B k row

    const float* Ap = A + (size_t)(m0 + am) * GK + akq * 16;
    const float* Wp = W + (size_t)bk * GN + n0 + bn;

    float acc[4][4][4];
    #pragma unroll
    for (int mi = 0; mi < 4; mi++)
        #pragma unroll
        for (int ni = 0; ni < 4; ni++)
            #pragma unroll
            for (int u = 0; u < 4; u++) acc[mi][ni][u] = 0.f;

    float4 ra[4], rb[4];
    // prefetch first tile
    #pragma unroll
    for (int j = 0; j < 4; j++) ra[j] = *(const float4*)(Ap + j * 4);
    #pragma unroll
    for (int j = 0; j < 4; j++) rb[j] = *(const float4*)(Wp + (size_t)(j * 8) * GN);

    for (int kb = 0; kb < GK; kb += 32) {
        // stage regs -> smem (with tf32 rounding)
        #pragma unroll
        for (int j = 0; j < 4; j++) {
            int k = akq * 16 + j * 4;
            As[k + 0][am] = f2tf32(ra[j].x);
            As[k + 1][am] = f2tf32(ra[j].y);
            As[k + 2][am] = f2tf32(ra[j].z);
            As[k + 3][am] = f2tf32(ra[j].w);
        }
        #pragma unroll
        for (int j = 0; j < 4; j++) {
            uint4 t;
            t.x = f2tf32(rb[j].x); t.y = f2tf32(rb[j].y);
            t.z = f2tf32(rb[j].z); t.w = f2tf32(rb[j].w);
            *(uint4*)&Bs[bk + j * 8][bn] = t;
        }
        __syncthreads();

        // prefetch next tile (overlaps with MMA below)
        if (kb + 32 < GK) {
            #pragma unroll
            for (int j = 0; j < 4; j++)
                ra[j] = *(const float4*)(Ap + kb + 32 + j * 4);
            #pragma unroll
            for (int j = 0; j < 4; j++)
                rb[j] = *(const float4*)(Wp + (size_t)(kb + 32 + j * 8) * GN);
        }

        #pragma unroll
        for (int kk = 0; kk < 32; kk += 8) {
            unsigned af[4][4], bf[4][2];
            #pragma unroll
            for (int mi = 0; mi < 4; mi++) {
                int mr = warpM * 64 + mi * 16 + gid;
                af[mi][0] = As[kk + tig][mr];
                af[mi][1] = As[kk + tig][mr + 8];
                af[mi][2] = As[kk + tig + 4][mr];
                af[mi][3] = As[kk + tig + 4][mr + 8];
            }
            #pragma unroll
            for (int ni = 0; ni < 4; ni++) {
                int nc = warpN * 32 + ni * 8 + gid;
                bf[ni][0] = Bs[kk + tig][nc];
                bf[ni][1] = Bs[kk + tig + 4][nc];
            }
            #pragma unroll
            for (int mi = 0; mi < 4; mi++)
                #pragma unroll
                for (int ni = 0; ni < 4; ni++) {
                    asm volatile(
                        "mma.sync.aligned.m16n8k8.row.col.f32.tf32.tf32.f32 "
                        "{%0,%1,%2,%3}, {%4,%5,%6,%7}, {%8,%9}, {%0,%1,%2,%3};"
                        : "+f"(acc[mi][ni][0]), "+f"(acc[mi][ni][1]),
                          "+f"(acc[mi][ni][2]), "+f"(acc[mi][ni][3])
                        : "r"(af[mi][0]), "r"(af[mi][1]),
                          "r"(af[mi][2]), "r"(af[mi][3]),
                          "r"(bf[ni][0]), "r"(bf[ni][1]));
                }
        }
        __syncthreads();
    }

    // Epilogue: bias (+ RoPE) (+ scatter)
    #pragma unroll
    for (int ni = 0; ni < 4; ni++) {
        const int c = n0 + warpN * 32 + ni * 8 + tig * 2;   // even column
        const float bv0 = bias[c], bv1 = bias[c + 1];
        #pragma unroll
        for (int mi = 0; mi < 4; mi++) {
            #pragma unroll
            for (int half = 0; half < 2; half++) {
                const int r = m0 + warpM * 64 + mi * 16 + gid + half * 8;
                float v0 = acc[mi][ni][half * 2 + 0] + bv0;
                float v1 = acc[mi][ni][half * 2 + 1] + bv1;
                const int bb = r >> 11;          // / S_
                const int s  = r & (S_ - 1);
                if (mode == 0) {
                    const int pi = (c & (HD_ - 1)) >> 1;
                    const float cs = g_cos[s * (HD_ / 2) + pi];
                    const float sn = g_sin[s * (HD_ / 2) + pi];
                    const float e = v0, o = v1;
                    v0 = e * cs - o * sn;
                    v1 = o * cs + e * sn;
                }
                float2 val; val.x = v0; val.y = v1;
                if (mode <= 1) {
                    const int h = (c >> 7) & (NH_ - 1);
                    const int d = c & (HD_ - 1);
                    *(float2*)(C + (size_t)((bb * NH_ + h) * S_ + s) * HD_ + d) = val;
                } else {
                    *(float2*)(C + (size_t)r * GN + c) = val;
                }
            }
        }
    }
}

// ---------------------------------------------------------------------------
// Flash attention (causal), fp32, BM=BN=64, 256 threads, online softmax.
// ---------------------------------------------------------------------------
#define BM 64
#define BN 64
#define QPAD 132
#define SPAD 68

__global__ __launch_bounds__(256) void attn_kernel(
    const float* __restrict__ q, const float* __restrict__ k,
    const float* __restrict__ v, float* __restrict__ ctx)
{
    extern __shared__ float sm[];
    float* Qs   = sm;
    float* Ks   = Qs + BM * QPAD;
    float* Vs   = Ks + BN * QPAD;
    float* Ss   = Vs + BN * QPAD;
    float* mrow = Ss + BM * SPAD;
    float* lrow = mrow + BM;
    float* frow = lrow + BM;

    const int tid = threadIdx.x;
    const int bh  = blockIdx.y;
    const int qt  = gridDim.x - 1 - blockIdx.x;
    const int q0  = qt * BM;

    const float* qp = q + ((size_t)bh * S_ + q0) * HD_;
    const float* kb = k + (size_t)bh * S_ * HD_;
    const float* vb = v + (size_t)bh * S_ * HD_;

    for (int t = tid; t < BM * 32; t += 256) {
        int r = t >> 5, c = (t & 31) * 4;
        *(float4*)&Qs[r * QPAD + c] = *(const float4*)&qp[r * HD_ + c];
    }
    if (tid < BM) { mrow[tid] = -1e30f; lrow[tid] = 0.f; }

    const int ty = tid >> 4, tx = tid & 15;
    float acc_o[4][8];
    #pragma unroll
    for (int i = 0; i < 4; i++)
        #pragma unroll
        for (int j = 0; j < 8; j++) acc_o[i][j] = 0.f;

    const int nkv = qt + 1;
    for (int kt = 0; kt < nkv; kt++) {
        const int k0 = kt * BN;
        __syncthreads();
        const float* kp = kb + (size_t)k0 * HD_;
        const float* vp = vb + (size_t)k0 * HD_;
        for (int t = tid; t < BN * 32; t += 256) {
            int r = t >> 5, c = (t & 31) * 4;
            *(float4*)&Ks[r * QPAD + c] = *(const float4*)&kp[r * HD_ + c];
            *(float4*)&Vs[r * QPAD + c] = *(const float4*)&vp[r * HD_ + c];
        }
        __syncthreads();

        {
            const int r0 = ty * 4, c0 = tx * 4;
            float accs[4][4];
            #pragma unroll
            for (int i = 0; i < 4; i++)
                #pragma unroll
                for (int j = 0; j < 4; j++) accs[i][j] = 0.f;

            for (int kk = 0; kk < HD_; kk += 4) {
                float4 qa[4], kv[4];
                #pragma unroll
                for (int i = 0; i < 4; i++)
                    qa[i] = *(const float4*)&Qs[(r0 + i) * QPAD + kk];
                #pragma unroll
                for (int j = 0; j < 4; j++)
                    kv[j] = *(const float4*)&Ks[(c0 + j) * QPAD + kk];
                #pragma unroll
                for (int i = 0; i < 4; i++)
                    #pragma unroll
                    for (int j = 0; j < 4; j++)
                        accs[i][j] += qa[i].x * kv[j].x + qa[i].y * kv[j].y
                                    + qa[i].z * kv[j].z + qa[i].w * kv[j].w;
            }
            #pragma unroll
            for (int i = 0; i < 4; i++) {
                int qi = q0 + r0 + i;
                #pragma unroll
                for (int j = 0; j < 4; j++) {
                    int kj = k0 + c0 + j;
                    float sv = accs[i][j] * SCALE_;
                    if (kj > qi) sv = -1e30f;
                    Ss[(r0 + i) * SPAD + c0 + j] = sv;
                }
            }
        }
        __syncthreads();

        {
            const int row = tid >> 2, g = tid & 3;
            float tmax = -1e30f;
            for (int j = g; j < BN; j += 4)
                tmax = fmaxf(tmax, Ss[row * SPAD + j]);
            tmax = fmaxf(tmax, __shfl_xor_sync(0xffffffffu, tmax, 1));
            tmax = fmaxf(tmax, __shfl_xor_sync(0xffffffffu, tmax, 2));
            float mold = mrow[row];
            float mnew = fmaxf(mold, tmax);
            float sum = 0.f;
            for (int j = g; j < BN; j += 4) {
                float p = __expf(Ss[row * SPAD + j] - mnew);
                Ss[row * SPAD + j] = p;
                sum += p;
            }
            sum += __shfl_xor_sync(0xffffffffu, sum, 1);
            sum += __shfl_xor_sync(0xffffffffu, sum, 2);
            if (g == 0) {
                float f = __expf(mold - mnew);
                lrow[row] = lrow[row] * f + sum;
                mrow[row] = mnew;
                frow[row] = f;
            }
        }
        __syncthreads();

        {
            const int r0 = ty * 4, c0 = tx * 8;
            float fr[4];
            #pragma unroll
            for (int i = 0; i < 4; i++) fr[i] = frow[r0 + i];
            #pragma unroll
            for (int i = 0; i < 4; i++)
                #pragma unroll
                for (int j = 0; j < 8; j++) acc_o[i][j] *= fr[i];

            for (int j = 0; j < BN; j++) {
                float p[4];
                #pragma unroll
                for (int i = 0; i < 4; i++) p[i] = Ss[(r0 + i) * SPAD + j];
                float4 v0 = *(const float4*)&Vs[j * QPAD + c0];
                float4 v1 = *(const float4*)&Vs[j * QPAD + c0 + 4];
                #pragma unroll
                for (int i = 0; i < 4; i++) {
                    acc_o[i][0] += p[i] * v0.x;
                    acc_o[i][1] += p[i] * v0.y;
                    acc_o[i][2] += p[i] * v0.z;
                    acc_o[i][3] += p[i] * v0.w;
                    acc_o[i][4] += p[i] * v1.x;
                    acc_o[i][5] += p[i] * v1.y;
                    acc_o[i][6] += p[i] * v1.z;
                    acc_o[i][7] += p[i] * v1.w;
                }
            }
        }
    }
    __syncthreads();

    const int b = bh >> 4, h = bh & 15;
    const int r0 = ty * 4, c0 = tx * 8;
    #pragma unroll
    for (int i = 0; i < 4; i++) {
        int r = r0 + i;
        float inv = 1.f / lrow[r];
        int s = q0 + r;
        float* dst = ctx + (size_t)(b * S_ + s) * DM_ + h * HD_ + c0;
        float o[8];
        #pragma unroll
        for (int j = 0; j < 8; j++) o[j] = acc_o[i][j] * inv;
        *(float4*)(dst + 0) = *(float4*)(o + 0);
        *(float4*)(dst + 4) = *(float4*)(o + 4);
    }
}

// ---------------------------------------------------------------------------
// Launch
// ---------------------------------------------------------------------------
extern "C" void kernel_launch(void* const* d_in, const int* in_sizes, int n_in,
                              void* d_out, int out_size)
{
    const float* hs = (const float*)d_in[0];
    const float* Wq = (const float*)d_in[1];
    const float* bq = (const float*)d_in[2];
    const float* Wk = (const float*)d_in[3];
    const float* bk = (const float*)d_in[4];
    const float* Wv = (const float*)d_in[5];
    const float* bv = (const float*)d_in[6];
    const float* Wo = (const float*)d_in[7];
    const float* bo = (const float*)d_in[8];
    float* out = (float*)d_out;

    float *qd, *kd, *vd, *ctxd;
    cudaGetSymbolAddress((void**)&qd,   g_q);
    cudaGetSymbolAddress((void**)&kd,   g_k);
    cudaGetSymbolAddress((void**)&vd,   g_v);
    cudaGetSymbolAddress((void**)&ctxd, g_ctx);

    static int smem_set = 0;
    const int attn_smem = (3 * BM * QPAD + BM * SPAD + 3 * BM) * (int)sizeof(float);
    if (!smem_set) {
        cudaFuncSetAttribute(attn_kernel,
                             cudaFuncAttributeMaxDynamicSharedMemorySize,
                             attn_smem);
        smem_set = 1;
    }

    rope_table_kernel<<<(S_ * (HD_ / 2) + 255) / 256, 256>>>();

    dim3 ggrid(GN / 128, 4096 / 128);
    tgemm_kernel<<<ggrid, 256>>>(hs, Wq, bq, qd, 0);
    tgemm_kernel<<<ggrid, 256>>>(hs, Wk, bk, kd, 0);
    tgemm_kernel<<<ggrid, 256>>>(hs, Wv, bv, vd, 1);

    dim3 agrid(S_ / BM, B_ * NH_);
    attn_kernel<<<agrid, 256, attn_smem>>>(qd, kd, vd, ctxd);

    tgemm_kernel<<<ggrid, 256>>>(ctxd, Wo, bo, out, 2);
}

// round 3
// speedup vs baseline: 2.9191x; 1.8482x over previous
#include <cuda_runtime.h>
#include <cuda_bf16.h>
#include <math.h>

// Problem constants
#define B_  2
#define S_  2048
#define DM_ 2048
#define NH_ 16
#define HD_ 128
#define BS_ (B_ * S_)
#define SCALE_ 0.08838834764831845f   // 1/sqrt(128)

// ---------------------------------------------------------------------------
// Scratch
// ---------------------------------------------------------------------------
__device__ float g_q[B_ * NH_ * S_ * HD_];   // [bh][s][d]  (pre-scaled by 1/sqrt(d))
__device__ float g_k[B_ * NH_ * S_ * HD_];
__device__ float g_v[B_ * NH_ * S_ * HD_];
__device__ float g_ctx[BS_ * DM_];           // [b*S+s][dm]
__device__ float g_cos[S_ * (HD_ / 2)];
__device__ float g_sin[S_ * (HD_ / 2)];

// ---------------------------------------------------------------------------
// RoPE table (double precision for accuracy)
// ---------------------------------------------------------------------------
__global__ void rope_table_kernel() {
    int idx = blockIdx.x * blockDim.x + threadIdx.x;
    if (idx >= S_ * (HD_ / 2)) return;
    int s = idx / (HD_ / 2);
    int i = idx % (HD_ / 2);
    double inv_freq = exp(-((double)(2 * i) / (double)HD_) * log(10000.0));
    double ang = (double)s * inv_freq;
    g_cos[idx] = (float)cos(ang);
    g_sin[idx] = (float)sin(ang);
}

__device__ __forceinline__ unsigned f2tf32(float x) {
    unsigned r;
    asm("cvt.rna.tf32.f32 %0, %1;" : "=r"(r) : "f"(x));
    return r;
}

#define MMA_TF32(C, a0, a1, a2, a3, b0, b1)                                   \
    asm volatile(                                                             \
        "mma.sync.aligned.m16n8k8.row.col.f32.tf32.tf32.f32 "                 \
        "{%0,%1,%2,%3}, {%4,%5,%6,%7}, {%8,%9}, {%0,%1,%2,%3};"               \
        : "+f"((C)[0]), "+f"((C)[1]), "+f"((C)[2]), "+f"((C)[3])              \
        : "r"(a0), "r"(a1), "r"(a2), "r"(a3), "r"(b0), "r"(b1))

// ---------------------------------------------------------------------------
// TF32 tensor-core GEMM: C[4096,2048] = A[4096,2048] @ W[2048,2048] + bias
// mode 0: rope + scale + scatter (Q)  mode 3: rope + scatter (K)
// mode 1: scatter (V)                 mode 2: plain row-major write (O proj)
// ---------------------------------------------------------------------------
#define GK 2048
#define GN 2048
#define SMS 136

__global__ __launch_bounds__(256) void tgemm_kernel(
    const float* __restrict__ A, const float* __restrict__ W,
    const float* __restrict__ bias, float* __restrict__ C, int mode)
{
    __shared__ unsigned As[32][SMS];   // [k][m]
    __shared__ unsigned Bs[32][SMS];   // [k][n]

    const int tid  = threadIdx.x;
    const int lane = tid & 31, wid = tid >> 5;
    const int warpM = wid >> 2, warpN = wid & 3;
    const int gid = lane >> 2, tig = lane & 3;
    const int m0 = blockIdx.y * 128, n0 = blockIdx.x * 128;

    const int am  = tid & 127;
    const int akq = tid >> 7;
    const int bn  = (tid & 31) * 4;
    const int bk  = tid >> 5;

    const float* Ap = A + (size_t)(m0 + am) * GK + akq * 16;
    const float* Wp = W + (size_t)bk * GN + n0 + bn;

    float acc[4][4][4];
    #pragma unroll
    for (int mi = 0; mi < 4; mi++)
        #pragma unroll
        for (int ni = 0; ni < 4; ni++)
            #pragma unroll
            for (int u = 0; u < 4; u++) acc[mi][ni][u] = 0.f;

    float4 ra[4], rb[4];
    #pragma unroll
    for (int j = 0; j < 4; j++) ra[j] = *(const float4*)(Ap + j * 4);
    #pragma unroll
    for (int j = 0; j < 4; j++) rb[j] = *(const float4*)(Wp + (size_t)(j * 8) * GN);

    for (int kb = 0; kb < GK; kb += 32) {
        #pragma unroll
        for (int j = 0; j < 4; j++) {
            int k = akq * 16 + j * 4;
            As[k + 0][am] = f2tf32(ra[j].x);
            As[k + 1][am] = f2tf32(ra[j].y);
            As[k + 2][am] = f2tf32(ra[j].z);
            As[k + 3][am] = f2tf32(ra[j].w);
        }
        #pragma unroll
        for (int j = 0; j < 4; j++) {
            uint4 t;
            t.x = f2tf32(rb[j].x); t.y = f2tf32(rb[j].y);
            t.z = f2tf32(rb[j].z); t.w = f2tf32(rb[j].w);
            *(uint4*)&Bs[bk + j * 8][bn] = t;
        }
        __syncthreads();

        if (kb + 32 < GK) {
            #pragma unroll
            for (int j = 0; j < 4; j++)
                ra[j] = *(const float4*)(Ap + kb + 32 + j * 4);
            #pragma unroll
            for (int j = 0; j < 4; j++)
                rb[j] = *(const float4*)(Wp + (size_t)(kb + 32 + j * 8) * GN);
        }

        #pragma unroll
        for (int kk = 0; kk < 32; kk += 8) {
            unsigned af[4][4], bf[4][2];
            #pragma unroll
            for (int mi = 0; mi < 4; mi++) {
                int mr = warpM * 64 + mi * 16 + gid;
                af[mi][0] = As[kk + tig][mr];
                af[mi][1] = As[kk + tig][mr + 8];
                af[mi][2] = As[kk + tig + 4][mr];
                af[mi][3] = As[kk + tig + 4][mr + 8];
            }
            #pragma unroll
            for (int ni = 0; ni < 4; ni++) {
                int nc = warpN * 32 + ni * 8 + gid;
                bf[ni][0] = Bs[kk + tig][nc];
                bf[ni][1] = Bs[kk + tig + 4][nc];
            }
            #pragma unroll
            for (int mi = 0; mi < 4; mi++)
                #pragma unroll
                for (int ni = 0; ni < 4; ni++)
                    MMA_TF32(acc[mi][ni], af[mi][0], af[mi][1], af[mi][2],
                             af[mi][3], bf[ni][0], bf[ni][1]);
        }
        __syncthreads();
    }

    // Epilogue: bias (+ RoPE) (+ scale for Q) (+ scatter)
    #pragma unroll
    for (int ni = 0; ni < 4; ni++) {
        const int c = n0 + warpN * 32 + ni * 8 + tig * 2;
        const float bv0 = bias[c], bv1 = bias[c + 1];
        #pragma unroll
        for (int mi = 0; mi < 4; mi++) {
            #pragma unroll
            for (int half = 0; half < 2; half++) {
                const int r = m0 + warpM * 64 + mi * 16 + gid + half * 8;
                float v0 = acc[mi][ni][half * 2 + 0] + bv0;
                float v1 = acc[mi][ni][half * 2 + 1] + bv1;
                const int bb = r >> 11;
                const int s  = r & (S_ - 1);
                if (mode == 0 || mode == 3) {
                    const int pi = (c & (HD_ - 1)) >> 1;
                    const float cs = g_cos[s * (HD_ / 2) + pi];
                    const float sn = g_sin[s * (HD_ / 2) + pi];
                    const float e = v0, o = v1;
                    v0 = e * cs - o * sn;
                    v1 = o * cs + e * sn;
                    if (mode == 0) { v0 *= SCALE_; v1 *= SCALE_; }
                }
                float2 val; val.x = v0; val.y = v1;
                if (mode != 2) {
                    const int h = (c >> 7) & (NH_ - 1);
                    const int d = c & (HD_ - 1);
                    *(float2*)(C + (size_t)((bb * NH_ + h) * S_ + s) * HD_ + d) = val;
                } else {
                    *(float2*)(C + (size_t)r * GN + c) = val;
                }
            }
        }
    }
}

// ---------------------------------------------------------------------------
// Flash attention (causal) on tf32 tensor cores.
// CTA: 64 q-rows, 4 warps x 16 rows. KV tiles of 64. HD=128 in registers.
// Q is pre-scaled by 1/sqrt(d) by the projection epilogue.
// ---------------------------------------------------------------------------
#define AST 132   // smem stride (mod 32 == 4 -> conflict-free fragment loads)

__global__ __launch_bounds__(128) void attn_mma_kernel(
    const float* __restrict__ q, const float* __restrict__ k,
    const float* __restrict__ v, float* __restrict__ ctx)
{
    extern __shared__ unsigned smu[];
    unsigned* Qs = smu;                // [64][AST]
    unsigned* Ks = Qs + 64 * AST;
    unsigned* Vs = Ks + 64 * AST;

    const int tid  = threadIdx.x;
    const int lane = tid & 31, wid = tid >> 5;
    const int gid = lane >> 2, tig = lane & 3;
    const int bh = blockIdx.y;
    const int qt = gridDim.x - 1 - blockIdx.x;   // heavy tiles first
    const int q0 = qt * 64;
    const int m0w = wid * 16;

    const float* qp = q + ((size_t)bh * S_ + q0) * HD_;
    const float* kb = k + (size_t)bh * S_ * HD_;
    const float* vb = v + (size_t)bh * S_ * HD_;

    // Load Q tile (already scaled)
    for (int t = tid; t < 64 * 32; t += 128) {
        int r = t >> 5, c = (t & 31) * 4;
        float4 f = *(const float4*)&qp[r * HD_ + c];
        uint4 u;
        u.x = f2tf32(f.x); u.y = f2tf32(f.y);
        u.z = f2tf32(f.z); u.w = f2tf32(f.w);
        *(uint4*)&Qs[r * AST + c] = u;
    }

    float oacc[16][4];
    #pragma unroll
    for (int ni = 0; ni < 16; ni++)
        #pragma unroll
        for (int u = 0; u < 4; u++) oacc[ni][u] = 0.f;
    float mx0 = -1e30f, mx1 = -1e30f, ls0 = 0.f, ls1 = 0.f;

    const int nkv = qt + 1;
    for (int kt = 0; kt < nkv; kt++) {
        const int k0 = kt * 64;
        __syncthreads();
        const float* kp = kb + (size_t)k0 * HD_;
        const float* vp = vb + (size_t)k0 * HD_;
        for (int t = tid; t < 64 * 32; t += 128) {
            int r = t >> 5, c = (t & 31) * 4;
            float4 fk = *(const float4*)&kp[r * HD_ + c];
            float4 fv = *(const float4*)&vp[r * HD_ + c];
            uint4 uk, uv;
            uk.x = f2tf32(fk.x); uk.y = f2tf32(fk.y);
            uk.z = f2tf32(fk.z); uk.w = f2tf32(fk.w);
            uv.x = f2tf32(fv.x); uv.y = f2tf32(fv.y);
            uv.z = f2tf32(fv.z); uv.w = f2tf32(fv.w);
            *(uint4*)&Ks[r * AST + c] = uk;
            *(uint4*)&Vs[r * AST + c] = uv;
        }
        __syncthreads();

        // ---- S = Q @ K^T (16x64 per warp) ----
        float sacc[8][4];
        #pragma unroll
        for (int ni = 0; ni < 8; ni++)
            #pragma unroll
            for (int u = 0; u < 4; u++) sacc[ni][u] = 0.f;

        #pragma unroll
        for (int ks = 0; ks < 16; ks++) {
            const int kk = ks * 8;
            unsigned a0 = Qs[(m0w + gid) * AST + kk + tig];
            unsigned a1 = Qs[(m0w + gid + 8) * AST + kk + tig];
            unsigned a2 = Qs[(m0w + gid) * AST + kk + tig + 4];
            unsigned a3 = Qs[(m0w + gid + 8) * AST + kk + tig + 4];
            #pragma unroll
            for (int ni = 0; ni < 8; ni++) {
                unsigned b0 = Ks[(ni * 8 + gid) * AST + kk + tig];
                unsigned b1 = Ks[(ni * 8 + gid) * AST + kk + tig + 4];
                MMA_TF32(sacc[ni], a0, a1, a2, a3, b0, b1);
            }
        }

        // ---- causal mask (diagonal tile only) ----
        if (kt == nkv - 1) {
            const int row0 = q0 + m0w + gid;
            #pragma unroll
            for (int ni = 0; ni < 8; ni++) {
                const int col = k0 + ni * 8 + tig * 2;
                if (col > row0)     sacc[ni][0] = -1e30f;
                if (col + 1 > row0) sacc[ni][1] = -1e30f;
                if (col > row0 + 8)     sacc[ni][2] = -1e30f;
                if (col + 1 > row0 + 8) sacc[ni][3] = -1e30f;
            }
        }

        // ---- online softmax (in accumulator layout) ----
        float rm0 = -1e30f, rm1 = -1e30f;
        #pragma unroll
        for (int ni = 0; ni < 8; ni++) {
            rm0 = fmaxf(rm0, fmaxf(sacc[ni][0], sacc[ni][1]));
            rm1 = fmaxf(rm1, fmaxf(sacc[ni][2], sacc[ni][3]));
        }
        rm0 = fmaxf(rm0, __shfl_xor_sync(0xffffffffu, rm0, 1));
        rm0 = fmaxf(rm0, __shfl_xor_sync(0xffffffffu, rm0, 2));
        rm1 = fmaxf(rm1, __shfl_xor_sync(0xffffffffu, rm1, 1));
        rm1 = fmaxf(rm1, __shfl_xor_sync(0xffffffffu, rm1, 2));

        const float mn0 = fmaxf(mx0, rm0), mn1 = fmaxf(mx1, rm1);
        const float f0 = __expf(mx0 - mn0), f1 = __expf(mx1 - mn1);
        float rs0 = 0.f, rs1 = 0.f;
        #pragma unroll
        for (int ni = 0; ni < 8; ni++) {
            float p0 = __expf(sacc[ni][0] - mn0);
            float p1 = __expf(sacc[ni][1] - mn0);
            float p2 = __expf(sacc[ni][2] - mn1);
            float p3 = __expf(sacc[ni][3] - mn1);
            sacc[ni][0] = p0; sacc[ni][1] = p1;
            sacc[ni][2] = p2; sacc[ni][3] = p3;
            rs0 += p0 + p1; rs1 += p2 + p3;
        }
        rs0 += __shfl_xor_sync(0xffffffffu, rs0, 1);
        rs0 += __shfl_xor_sync(0xffffffffu, rs0, 2);
        rs1 += __shfl_xor_sync(0xffffffffu, rs1, 1);
        rs1 += __shfl_xor_sync(0xffffffffu, rs1, 2);
        ls0 = ls0 * f0 + rs0; ls1 = ls1 * f1 + rs1;
        mx0 = mn0; mx1 = mn1;

        #pragma unroll
        for (int ni = 0; ni < 16; ni++) {
            oacc[ni][0] *= f0; oacc[ni][1] *= f0;
            oacc[ni][2] *= f1; oacc[ni][3] *= f1;
        }

        // ---- O += P @ V ----
        #pragma unroll
        for (int kk = 0; kk < 8; kk++) {
            const int l1 = (gid << 2) | (tig >> 1);
            const int l2 = l1 + 2;
            float v00 = __shfl_sync(0xffffffffu, sacc[kk][0], l1);
            float v01 = __shfl_sync(0xffffffffu, sacc[kk][1], l1);
            float v10 = __shfl_sync(0xffffffffu, sacc[kk][2], l1);
            float v11 = __shfl_sync(0xffffffffu, sacc[kk][3], l1);
            float w00 = __shfl_sync(0xffffffffu, sacc[kk][0], l2);
            float w01 = __shfl_sync(0xffffffffu, sacc[kk][1], l2);
            float w10 = __shfl_sync(0xffffffffu, sacc[kk][2], l2);
            float w11 = __shfl_sync(0xffffffffu, sacc[kk][3], l2);
            const bool odd = tig & 1;
            unsigned pa0 = f2tf32(odd ? v01 : v00);
            unsigned pa1 = f2tf32(odd ? v11 : v10);
            unsigned pa2 = f2tf32(odd ? w01 : w00);
            unsigned pa3 = f2tf32(odd ? w11 : w10);
            #pragma unroll
            for (int ni = 0; ni < 16; ni++) {
                unsigned b0 = Vs[(kk * 8 + tig) * AST + ni * 8 + gid];
                unsigned b1 = Vs[(kk * 8 + tig + 4) * AST + ni * 8 + gid];
                MMA_TF32(oacc[ni], pa0, pa1, pa2, pa3, b0, b1);
            }
        }
    }

    // ---- normalize + write ctx ----
    const float inv0 = 1.f / ls0, inv1 = 1.f / ls1;
    const int b = bh >> 4, h = bh & 15;
    const int s0 = q0 + m0w + gid;
    #pragma unroll
    for (int ni = 0; ni < 16; ni++) {
        const int col = ni * 8 + tig * 2;
        float2 r0; r0.x = oacc[ni][0] * inv0; r0.y = oacc[ni][1] * inv0;
        float2 r1; r1.x = oacc[ni][2] * inv1; r1.y = oacc[ni][3] * inv1;
        *(float2*)(ctx + (size_t)(b * S_ + s0) * DM_ + h * HD_ + col) = r0;
        *(float2*)(ctx + (size_t)(b * S_ + s0 + 8) * DM_ + h * HD_ + col) = r1;
    }
}

// ---------------------------------------------------------------------------
// Launch
// ---------------------------------------------------------------------------
extern "C" void kernel_launch(void* const* d_in, const int* in_sizes, int n_in,
                              void* d_out, int out_size)
{
    const float* hs = (const float*)d_in[0];
    const float* Wq = (const float*)d_in[1];
    const float* bq = (const float*)d_in[2];
    const float* Wk = (const float*)d_in[3];
    const float* bk = (const float*)d_in[4];
    const float* Wv = (const float*)d_in[5];
    const float* bv = (const float*)d_in[6];
    const float* Wo = (const float*)d_in[7];
    const float* bo = (const float*)d_in[8];
    float* out = (float*)d_out;

    float *qd, *kd, *vd, *ctxd;
    cudaGetSymbolAddress((void**)&qd,   g_q);
    cudaGetSymbolAddress((void**)&kd,   g_k);
    cudaGetSymbolAddress((void**)&vd,   g_v);
    cudaGetSymbolAddress((void**)&ctxd, g_ctx);

    static int smem_set = 0;
    const int attn_smem = 3 * 64 * AST * (int)sizeof(unsigned);
    if (!smem_set) {
        cudaFuncSetAttribute(attn_mma_kernel,
                             cudaFuncAttributeMaxDynamicSharedMemorySize,
                             attn_smem);
        smem_set = 1;
    }

    rope_table_kernel<<<(S_ * (HD_ / 2) + 255) / 256, 256>>>();

    dim3 ggrid(GN / 128, 4096 / 128);
    tgemm_kernel<<<ggrid, 256>>>(hs, Wq, bq, qd, 0);   // Q: rope + scale
    tgemm_kernel<<<ggrid, 256>>>(hs, Wk, bk, kd, 3);   // K: rope
    tgemm_kernel<<<ggrid, 256>>>(hs, Wv, bv, vd, 1);   // V

    dim3 agrid(S_ / 64, B_ * NH_);
    attn_mma_kernel<<<agrid, 128, attn_smem>>>(qd, kd, vd, ctxd);

    tgemm_kernel<<<ggrid, 256>>>(ctxd, Wo, bo, out, 2);
}